// round 15
// baseline (speedup 1.0000x reference)
#include <cuda_runtime.h>

// PS-ROI Pooling, float4 windows, shared masks, d-channel pairing for MLP.
// features [4,1029,64,64] f32, rois [1024,5] f32, out [1024,21,7,7] f32.
//
// NUMERICS CONTRACT (frozen, validated R10-R14: rel_err 9.5e-7):
//  - bounds: separate __fmul_rn/__fadd_rn, rintf, __fdividef (div.full.f32,
//    XLA:GPU's fast f32 division) for bin = roi/7 and final s/area.
//  - window sums exact f32 (order-insensitive at this tolerance).
//
// PERF (R15): outputs d*49+g and (d+11)*49+g share bin g -> identical
// window/masks. One thread processes the pair: 4-6 independent LDG.128 per
// loop body from two planes (2 outputs x 2 rows x nc chunks) with shared
// mask registers -> ~2x in-flight loads vs v14 at ~zero register cost.
// 539 items/ROI = 49 bins x 11 d-groups; solo group (d=10) aliases both
// pointers (dup loads hit L1) to keep the hot path branch-free.

#define BATCH 4
#define POOLED 7
#define OUTPUT_DIM 21
#define CHANNELS (OUTPUT_DIM * POOLED * POOLED)  // 1029
#define H 64
#define W 64
#define SPATIAL_SCALE 0.0625f
#define NUM_ROIS 1024
#define PER_ROI CHANNELS                         // 1029
#define PLANE (H * W)
#define ROWQ (W / 4)                             // 16 float4 per row
#define NITEMS 539                               // 49 bins * 11 d-groups
#define SPLIT 270                                // items for blockIdx.y==0

#define ACC4(acc, v, m)                      \
    acc##x = fmaf((v).x, (m).x, acc##x);     \
    acc##y = fmaf((v).y, (m).y, acc##y);     \
    acc##z = fmaf((v).z, (m).z, acc##z);     \
    acc##w = fmaf((v).w, (m).w, acc##w);

__global__ __launch_bounds__(256, 5)
void psroi_v15_kernel(const float* __restrict__ features,
                      const float* __restrict__ rois,
                      float* __restrict__ out)
{
    __shared__ int    sh_hs[POOLED], sh_he[POOLED];
    __shared__ int    sh_fc[POOLED], sh_nc[POOLED];
    __shared__ float  sh_area_h[POOLED], sh_area_w[POOLED];
    __shared__ float4 sh_msk[POOLED][3];
    __shared__ int    sh_b;

    const int n   = blockIdx.x;
    const int tid = threadIdx.x;

    if (tid < 2 * POOLED) {
        const float* r = rois + n * 5;
        const int axis = tid / POOLED;   // 0 -> h (y: r[2],r[4]), 1 -> w (x: r[1],r[3])
        const int p    = tid % POOLED;

        float c_start = axis ? r[1] : r[2];
        float c_end   = axis ? r[3] : r[4];

        float rs = __fmul_rn(rintf(c_start), SPATIAL_SCALE);
        float re = __fmul_rn(rintf(__fadd_rn(c_end, 1.0f)), SPATIAL_SCALE);
        float roi_sz = fmaxf(__fsub_rn(re, rs), 0.1f);
        float bin    = __fdividef(roi_sz, (float)POOLED);   // div.full.f32 (XLA match)

        float fp = (float)p;
        float v0 = __fadd_rn(__fmul_rn(fp, bin), rs);
        float v1 = __fadd_rn(__fmul_rn(__fadd_rn(fp, 1.0f), bin), rs);

        int s = (int)fminf(fmaxf(floorf(v0), 0.0f), 64.0f);
        int e = (int)fminf(fmaxf(ceilf (v1), 0.0f), 64.0f);

        if (axis == 0) {
            sh_hs[p] = s; sh_he[p] = e;
            sh_area_h[p] = (float)(e - s);
        } else {
            int fc = s >> 2;
            int lc = (e - 1) >> 2;            // empty -> lc < fc
            sh_fc[p] = fc;
            sh_nc[p] = lc - fc + 1;
            sh_area_w[p] = (float)(e - s);
#pragma unroll
            for (int k = 0; k < 3; ++k) {
                int b0 = (fc + k) * 4;
                float4 m;
                m.x = (b0 + 0 >= s && b0 + 0 < e) ? 1.0f : 0.0f;
                m.y = (b0 + 1 >= s && b0 + 1 < e) ? 1.0f : 0.0f;
                m.z = (b0 + 2 >= s && b0 + 2 < e) ? 1.0f : 0.0f;
                m.w = (b0 + 3 >= s && b0 + 3 < e) ? 1.0f : 0.0f;
                sh_msk[p][k] = m;
            }
        }
        if (tid == 0) sh_b = (int)r[0];
    }
    __syncthreads();

    const float* base = features + (size_t)sh_b * CHANNELS * PLANE;
    float* out_roi = out + (size_t)n * PER_ROI;

    const int it_start = blockIdx.y ? SPLIT : 0;
    const int it_end   = blockIdx.y ? NITEMS : SPLIT;

    for (int j = it_start + tid; j < it_end; j += 256) {
        const int g  = j % 49;           // bin index = ph*7 + pw
        const int dg = j / 49;           // d-group: {dg, dg+11}, dg==10 solo
        const int pw = g % POOLED;
        const int ph = g / POOLED;
        const bool dual = (dg < 10);

        const int hs = sh_hs[ph], he = sh_he[ph];
        const int fc = sh_fc[pw], nc = sh_nc[pw];

        const int oA = dg * 49 + g;
        const int oB = oA + 11 * 49;     // used only if dual

        const float4* pA = (const float4*)(base + (size_t)oA * PLANE) + fc;
        const float4* pB = dual ? (const float4*)(base + (size_t)oB * PLANE) + fc
                                : pA;    // alias: dup loads are L1 hits

        float4 m0 = sh_msk[pw][0];
        float Ax = 0.0f, Ay = 0.0f, Az = 0.0f, Aw = 0.0f;
        float Bx = 0.0f, By = 0.0f, Bz = 0.0f, Bw = 0.0f;

        if (nc == 1) {
            int h = hs;
            for (; h + 2 <= he; h += 2) {
                float4 vA0 = __ldg(pA + h * ROWQ);
                float4 vA1 = __ldg(pA + (h + 1) * ROWQ);
                float4 vB0 = __ldg(pB + h * ROWQ);
                float4 vB1 = __ldg(pB + (h + 1) * ROWQ);
                ACC4(A, vA0, m0); ACC4(A, vA1, m0);
                ACC4(B, vB0, m0); ACC4(B, vB1, m0);
            }
            if (h < he) {
                float4 vA = __ldg(pA + h * ROWQ);
                float4 vB = __ldg(pB + h * ROWQ);
                ACC4(A, vA, m0); ACC4(B, vB, m0);
            }
        } else if (nc == 2) {
            float4 m1 = sh_msk[pw][1];
            for (int h = hs; h < he; ++h) {
                const float4* rA = pA + h * ROWQ;
                const float4* rB = pB + h * ROWQ;
                float4 vA0 = __ldg(rA);
                float4 vA1 = __ldg(rA + 1);
                float4 vB0 = __ldg(rB);
                float4 vB1 = __ldg(rB + 1);
                ACC4(A, vA0, m0); ACC4(A, vA1, m1);
                ACC4(B, vB0, m0); ACC4(B, vB1, m1);
            }
        } else {
            float4 m1 = sh_msk[pw][1];
            float4 m2 = sh_msk[pw][2];
            for (int h = hs; h < he; ++h) {
                const float4* rA = pA + h * ROWQ;
                const float4* rB = pB + h * ROWQ;
                float4 vA0 = __ldg(rA);
                float4 vA1 = __ldg(rA + 1);
                float4 vA2 = __ldg(rA + 2);
                float4 vB0 = __ldg(rB);
                float4 vB1 = __ldg(rB + 1);
                float4 vB2 = __ldg(rB + 2);
                ACC4(A, vA0, m0); ACC4(A, vA1, m1); ACC4(A, vA2, m2);
                ACC4(B, vB0, m0); ACC4(B, vB1, m1); ACC4(B, vB2, m2);
            }
        }

        float sA = (Ax + Ay) + (Az + Aw);
        float sB = (Bx + By) + (Bz + Bw);

        float area = sh_area_h[ph] * sh_area_w[pw];
        float inv_ok = (area > 0.0f) ? 1.0f : 0.0f;  // just for clarity; branch below

        out_roi[oA] = (area > 0.0f) ? __fdividef(sA, area) : 0.0f;
        if (dual)
            out_roi[oB] = (area > 0.0f) ? __fdividef(sB, area) : 0.0f;
        (void)inv_ok;
    }
}

extern "C" void kernel_launch(void* const* d_in, const int* in_sizes, int n_in,
                              void* d_out, int out_size)
{
    const float* features = (const float*)d_in[0];
    const float* rois     = (const float*)d_in[1];
    float* out            = (float*)d_out;

    dim3 grid(NUM_ROIS, 2);
    psroi_v15_kernel<<<grid, 256>>>(features, rois, out);
}